// round 6
// baseline (speedup 1.0000x reference)
#include <cuda_runtime.h>
#include <cstdint>
#include <cstddef>

// ============================================================================
// GraphKANLayer on GB300 — baseline-PTX tensor path (no tcgen05: the harness
// targets compute_103, which rejects all 'a'-suffix instructions).
//
//   W2[o,f] = INV_SQRT2 * nl_w[f] * w_out[o,f]
//   c[o]    = b_out[o] + sum_f nl_b[f] * w_out[o,f]
//   Yt[b*64+o, j] = sum_f x[b,j,f] * W2[o,f]        (prep, fp32; tf32-rounded)
//   out[b,m,o] = sum_j adj[m,j]*Yt[b*64+o,j] + c[o] (tf32 mma.sync GEMM)
//
// GEMM M=8192 N=256 K=8192. 128 CTAs (64 m x 2 n), tile 128x128, 8 warps of
// 64x32, K-chunk 64 (2 sub-chunks of 32 = one 128B SW atom per row),
// 3-stage cp.async pipeline, ldmatrix.x4 fragment loads, fused bias epilogue.
// ============================================================================

#define FEAT 64
#define ODIM 64
#define NODES 8192
#define BATCH 4
#define NCOLS 256
#define INV_SQRT2F 0.70710678118654752440f

#define MT 128
#define NT 128
#define KCH 64                      // k per chunk
#define SUBK 32                     // k per sub-chunk (128B rows)
#define STAGES 3
#define NCH (NODES / KCH)           // 128
#define A_SUB 16384                 // 128 rows * 128B
#define SUB_BYTES 32768             // A_SUB + B_SUB
#define STAGE_BYTES 65536
#define SMEM_DYN (STAGES * STAGE_BYTES)   // 192 KB

#define JT 16                       // prep1 j-tile

// ---- scratch (static device globals; cudaMalloc forbidden) ----
__device__ float g_W2[ODIM * FEAT];
__device__ float g_c[ODIM];
__device__ float g_Yt[(size_t)NCOLS * NODES];   // 8 MB, [n][j] K-major

// ---------------------------------------------------------------------------
// PTX helpers (all baseline ISA: sm_80/sm_90 features only)
// ---------------------------------------------------------------------------
static __device__ __forceinline__ uint32_t smem_u32(const void* p) {
    uint32_t a;
    asm("{ .reg .u64 t; cvta.to.shared.u64 t, %1; cvt.u32.u64 %0, t; }"
        : "=r"(a) : "l"(p));
    return a;
}

static __device__ __forceinline__ void cp_async16(uint32_t dst, const void* src) {
    asm volatile("cp.async.cg.shared.global [%0], [%1], 16;"
                 :: "r"(dst), "l"(src) : "memory");
}
static __device__ __forceinline__ void cp_commit() {
    asm volatile("cp.async.commit_group;" ::: "memory");
}
template <int N>
static __device__ __forceinline__ void cp_wait() {
    asm volatile("cp.async.wait_group %0;" :: "n"(N) : "memory");
}

static __device__ __forceinline__ void ldsm_x4(uint32_t& r0, uint32_t& r1,
                                               uint32_t& r2, uint32_t& r3,
                                               uint32_t addr) {
    asm volatile("ldmatrix.sync.aligned.m8n8.x4.shared.b16 {%0,%1,%2,%3}, [%4];"
                 : "=r"(r0), "=r"(r1), "=r"(r2), "=r"(r3) : "r"(addr));
}

static __device__ __forceinline__ void mma_tf32(float* d, const uint32_t* a,
                                                const uint32_t* b) {
    asm volatile(
        "mma.sync.aligned.m16n8k8.row.col.f32.tf32.tf32.f32 "
        "{%0,%1,%2,%3}, {%4,%5,%6,%7}, {%8,%9}, {%0,%1,%2,%3};"
        : "+f"(d[0]), "+f"(d[1]), "+f"(d[2]), "+f"(d[3])
        : "r"(a[0]), "r"(a[1]), "r"(a[2]), "r"(a[3]), "r"(b[0]), "r"(b[1]));
}

static __device__ __forceinline__ float to_tf32_rna(float v) {
    uint32_t t;
    asm("cvt.rna.tf32.f32 %0, %1;" : "=r"(t) : "f"(v));
    return __uint_as_float(t);
}

static __device__ __forceinline__ uint32_t swz(uint32_t off) {
    return off ^ ((off >> 3) & 0x70);
}

// ---------------------------------------------------------------------------
// prep0: W2 and c
// ---------------------------------------------------------------------------
__global__ void prep0_kernel(const float* __restrict__ nl_w,
                             const float* __restrict__ nl_b,
                             const float* __restrict__ w_out,
                             const float* __restrict__ b_out) {
    int o = threadIdx.x;  // 64 threads
    float acc = b_out[o];
    for (int f = 0; f < FEAT; f++) {
        float w = w_out[o * FEAT + f];
        g_W2[o * FEAT + f] = INV_SQRT2F * nl_w[f] * w;
        acc += nl_b[f] * w;
    }
    g_c[o] = acc;
}

// ---------------------------------------------------------------------------
// prep1: Yt[b*64+o][j] = sum_f x[b,j,f] * W2[o,f]  (tf32-rounded output)
// ---------------------------------------------------------------------------
__global__ void __launch_bounds__(256) prep1_kernel(const float* __restrict__ x) {
    __shared__ float xs[BATCH][JT][FEAT];
    __shared__ float w2s[ODIM * (FEAT + 1)];
    const int tid = threadIdx.x;
    const int j0 = blockIdx.x * JT;

    for (int i = tid; i < ODIM * FEAT; i += 256)
        w2s[(i >> 6) * (FEAT + 1) + (i & 63)] = g_W2[i];

    for (int i4 = tid; i4 < BATCH * JT * (FEAT / 4); i4 += 256) {
        int b = i4 >> 8;
        int r = i4 & 255;
        int j = r >> 4;
        int f4 = r & 15;
        ((float4*)&xs[b][j][0])[f4] =
            ((const float4*)(x + ((size_t)b * NODES + j0 + j) * FEAT))[f4];
    }
    __syncthreads();

    const int o = tid & 63;
    const int b = tid >> 6;

    float w2r[FEAT];
#pragma unroll
    for (int f = 0; f < FEAT; f++) w2r[f] = w2s[o * (FEAT + 1) + f];

    float outv[JT];
#pragma unroll
    for (int j = 0; j < JT; j++) {
        float acc = 0.f;
#pragma unroll
        for (int f4 = 0; f4 < FEAT / 4; f4++) {
            float4 xv = ((float4*)&xs[b][j][0])[f4];
            acc += xv.x * w2r[f4 * 4 + 0];
            acc += xv.y * w2r[f4 * 4 + 1];
            acc += xv.z * w2r[f4 * 4 + 2];
            acc += xv.w * w2r[f4 * 4 + 3];
        }
        outv[j] = to_tf32_rna(acc);
    }

    float* dst = g_Yt + (size_t)(b * ODIM + o) * NODES + j0;
#pragma unroll
    for (int q = 0; q < JT / 4; q++)
        ((float4*)dst)[q] = make_float4(outv[q * 4 + 0], outv[q * 4 + 1],
                                        outv[q * 4 + 2], outv[q * 4 + 3]);
}

// ---------------------------------------------------------------------------
// Main GEMM: out = adj @ Yt^T + c
// grid 128 = 64 m-tiles x 2 n-tiles, block 256 (8 warps: 2 m x 4 n, 64x32 each)
// ---------------------------------------------------------------------------
__global__ void __launch_bounds__(256, 1)
gemm_kernel(const float* __restrict__ adj, float* __restrict__ out) {
    extern __shared__ char dynsmem[];
    __shared__ float sc[ODIM];

    const int tid = threadIdx.x;
    const int wid = tid >> 5;
    const int lane = tid & 31;
    const int m0 = (blockIdx.x >> 1) * MT;
    const int n0 = (blockIdx.x & 1) * NT;
    const int wm = wid >> 2;     // 0..1  (m band of 64)
    const int wn = wid & 3;      // 0..3  (n band of 32)

    const uint32_t smem0 = smem_u32(dynsmem);

    if (tid < ODIM) sc[tid] = g_c[tid];

    // Pre-swizzled per-lane fragment base offsets (within A / B block).
    // A (m16k8 tile mi): ldmatrix.x4 matrices = rows[0:8)h0, rows[8:16)h0,
    //                    rows[0:8)h1, rows[8:16)h1
    uint32_t pa[4];
    {
        int r15 = lane & 15;
        int h = lane >> 4;
#pragma unroll
        for (int mi = 0; mi < 4; mi++) {
            uint32_t off = (uint32_t)((wm * 64 + mi * 16 + r15) * 128 + h * 16);
            pa[mi] = swz(off);
        }
    }
    // B (two n8 tiles per ldmatrix.x4): matrices = tile_even h0, tile_even h1,
    //                                   tile_odd h0, tile_odd h1
    uint32_t pb[2];
    {
        int tile_sel = lane >> 4;          // 0: even tile, 1: odd tile
        int h = (lane >> 3) & 1;
        int rn = lane & 7;
#pragma unroll
        for (int nj = 0; nj < 2; nj++) {
            uint32_t off = (uint32_t)((wn * 32 + (nj * 2 + tile_sel) * 8 + rn) * 128 + h * 16);
            pb[nj] = swz(off);
        }
    }

    float acc[4][4][4];
#pragma unroll
    for (int mi = 0; mi < 4; mi++)
#pragma unroll
        for (int ni = 0; ni < 4; ni++)
#pragma unroll
            for (int q = 0; q < 4; q++) acc[mi][ni][q] = 0.f;

    // cooperative 64k-chunk load: 4096 x 16B segments, 16 per thread
    auto load_chunk = [&](int c) {
        const uint32_t sbase = smem0 + (uint32_t)(c % STAGES) * STAGE_BYTES;
        const int kb = c * KCH;
#pragma unroll
        for (int t = 0; t < 16; t++) {
            int idx = tid + t * 256;            // 0..4095
            int mat = idx >> 11;                // 0=A(adj), 1=B(Yt)
            int rest = idx & 2047;
            int sub = rest >> 10;               // k sub-chunk
            int r = (rest >> 3) & 127;          // row
            int seg = rest & 7;                 // 16B segment
            uint32_t dst = sbase + (uint32_t)sub * SUB_BYTES +
                           (uint32_t)mat * A_SUB +
                           swz((uint32_t)(r * 128 + seg * 16));
            const float* src = mat
                ? g_Yt + (size_t)(n0 + r) * NODES + kb + sub * SUBK + seg * 4
                : adj + (size_t)(m0 + r) * NODES + kb + sub * SUBK + seg * 4;
            cp_async16(dst, src);
        }
    };

    // prologue
    load_chunk(0); cp_commit();
    load_chunk(1); cp_commit();

    uint32_t fa[2][4][4];
    uint32_t fb[2][4][2];

    for (int i = 0; i < NCH; i++) {
        const int c = i + STAGES - 1;
        if (c < NCH) load_chunk(c);
        cp_commit();                 // group per iteration (empty at tail)
        cp_wait<STAGES - 1>();       // chunk i resident
        __syncthreads();

        const uint32_t sbase = smem0 + (uint32_t)(i % STAGES) * STAGE_BYTES;

        auto fetch = [&](int s8, int buf) {
            const uint32_t b2 = sbase + (uint32_t)(s8 >> 2) * SUB_BYTES;
            const uint32_t xo = (uint32_t)(s8 & 3) << 5;   // k8*32B, XOR-safe
#pragma unroll
            for (int mi = 0; mi < 4; mi++)
                ldsm_x4(fa[buf][mi][0], fa[buf][mi][1],
                        fa[buf][mi][2], fa[buf][mi][3],
                        b2 + (pa[mi] ^ xo));
#pragma unroll
            for (int nj = 0; nj < 2; nj++) {
                uint32_t r0, r1, r2, r3;
                ldsm_x4(r0, r1, r2, r3, b2 + A_SUB + (pb[nj] ^ xo));
                fb[buf][nj * 2 + 0][0] = r0;
                fb[buf][nj * 2 + 0][1] = r1;
                fb[buf][nj * 2 + 1][0] = r2;
                fb[buf][nj * 2 + 1][1] = r3;
            }
        };

        fetch(0, 0);
#pragma unroll
        for (int s8 = 0; s8 < 8; s8++) {
            if (s8 < 7) fetch(s8 + 1, (s8 + 1) & 1);
            const int bf = s8 & 1;
#pragma unroll
            for (int mi = 0; mi < 4; mi++)
#pragma unroll
                for (int ni = 0; ni < 4; ni++)
                    mma_tf32(acc[mi][ni], fa[bf][mi], fb[bf][ni]);
        }
        __syncthreads();
    }

    // epilogue: bias + scatter to (b, node, o)
    const int qr = lane >> 2;
    const int qc = lane & 3;
#pragma unroll
    for (int mi = 0; mi < 4; mi++) {
        const int row0 = m0 + wm * 64 + mi * 16 + qr;
#pragma unroll
        for (int ni = 0; ni < 4; ni++) {
            const int ng = n0 + wn * 32 + ni * 8 + qc * 2;
            const int b = ng >> 6;
            const int o = ng & 63;
            const float c0 = sc[o];
            const float c1 = sc[o + 1];
            float* d0 = out + ((size_t)b * NODES + row0) * ODIM + o;
            float2 v0 = make_float2(acc[mi][ni][0] + c0, acc[mi][ni][1] + c1);
            float2 v1 = make_float2(acc[mi][ni][2] + c0, acc[mi][ni][3] + c1);
            *(float2*)d0 = v0;
            *(float2*)(d0 + 8 * ODIM) = v1;   // row0 + 8
        }
    }
}

// ---------------------------------------------------------------------------
// launch
// ---------------------------------------------------------------------------
extern "C" void kernel_launch(void* const* d_in, const int* in_sizes, int n_in,
                              void* d_out, int out_size) {
    (void)in_sizes; (void)n_in; (void)out_size;
    const float* x     = (const float*)d_in[0];
    const float* adj   = (const float*)d_in[1];
    const float* nl_w  = (const float*)d_in[2];
    const float* nl_b  = (const float*)d_in[3];
    const float* w_out = (const float*)d_in[4];
    const float* b_out = (const float*)d_in[5];
    float* out = (float*)d_out;

    prep0_kernel<<<1, 64>>>(nl_w, nl_b, w_out, b_out);
    prep1_kernel<<<NODES / JT, 256>>>(x);

    static bool attr_set = false;
    if (!attr_set) {
        cudaFuncSetAttribute(gemm_kernel,
                             cudaFuncAttributeMaxDynamicSharedMemorySize, SMEM_DYN);
        attr_set = true;
    }
    gemm_kernel<<<128, 256, SMEM_DYN>>>(adj, out);
}

// round 8
// speedup vs baseline: 1.1702x; 1.1702x over previous
#include <cuda_runtime.h>
#include <cuda_fp16.h>
#include <cstdint>
#include <cstddef>

// ============================================================================
// GraphKANLayer on GB300 — fp16 tensor-core path (baseline PTX ISA only;
// compute_103 target rejects tcgen05).
//
//   W2[o,f] = INV_SQRT2 * nl_w[f] * w_out[o,f]
//   c[o]    = b_out[o] + sum_f nl_b[f] * w_out[o,f]
//   adj_h   = fp16(adj * 2^13)                      (conv kernel, RN, exact scale)
//   Yt_h[b*64+o, j] = fp16(sum_f x[b,j,f]*W2[o,f])  (prep1, fp32 math)
//   out[b,m,o] = 2^-13 * (adj_h @ Yt_h^T)[.] + c[o] (m16n8k16 fp16 MMA, f32 acc)
//
// GEMM M=8192 N=256 K=8192. 128 CTAs (64 m x 2 n), tile 128x128, 8 warps of
// 64x32, K-chunk 64 (= one 128B swizzle atom per fp16 row), 6-stage cp.async
// pipeline, ldmatrix.x4 fragments, fused bias+rescale epilogue.
// ============================================================================

#define FEAT 64
#define ODIM 64
#define NODES 8192
#define BATCH 4
#define NCOLS 256
#define INV_SQRT2F 0.70710678118654752440f
#define ADJ_SCALE 8192.0f
#define OUT_SCALE (1.0f / 8192.0f)

#define MT 128
#define NT 128
#define KCH 64                       // k per chunk: 64 halfs = 128B rows
#define STAGES 6
#define NCH (NODES / KCH)            // 128
#define A_BYTES (MT * KCH * 2)       // 16384
#define STAGE_BYTES (2 * A_BYTES)    // 32768
#define SMEM_DYN (STAGES * STAGE_BYTES)   // 192 KB

#define JT 16                        // prep1 j-tile

// ---- scratch (static device globals; cudaMalloc forbidden) ----
__device__ __align__(16) __half g_adj_h[(size_t)NODES * NODES];   // 128 MB
__device__ __align__(16) __half g_Yt_h[(size_t)NCOLS * NODES];    // 4 MB

// ---------------------------------------------------------------------------
// PTX helpers (baseline ISA)
// ---------------------------------------------------------------------------
static __device__ __forceinline__ uint32_t smem_u32(const void* p) {
    uint32_t a;
    asm("{ .reg .u64 t; cvta.to.shared.u64 t, %1; cvt.u32.u64 %0, t; }"
        : "=r"(a) : "l"(p));
    return a;
}

static __device__ __forceinline__ void cp_async16(uint32_t dst, const void* src) {
    asm volatile("cp.async.cg.shared.global [%0], [%1], 16;"
                 :: "r"(dst), "l"(src) : "memory");
}
static __device__ __forceinline__ void cp_commit() {
    asm volatile("cp.async.commit_group;" ::: "memory");
}
template <int N>
static __device__ __forceinline__ void cp_wait() {
    asm volatile("cp.async.wait_group %0;" :: "n"(N) : "memory");
}

static __device__ __forceinline__ void ldsm_x4(uint32_t& r0, uint32_t& r1,
                                               uint32_t& r2, uint32_t& r3,
                                               uint32_t addr) {
    asm volatile("ldmatrix.sync.aligned.m8n8.x4.shared.b16 {%0,%1,%2,%3}, [%4];"
                 : "=r"(r0), "=r"(r1), "=r"(r2), "=r"(r3) : "r"(addr));
}

static __device__ __forceinline__ void mma_f16(float* d, const uint32_t* a,
                                               const uint32_t* b) {
    asm volatile(
        "mma.sync.aligned.m16n8k16.row.col.f32.f16.f16.f32 "
        "{%0,%1,%2,%3}, {%4,%5,%6,%7}, {%8,%9}, {%0,%1,%2,%3};"
        : "+f"(d[0]), "+f"(d[1]), "+f"(d[2]), "+f"(d[3])
        : "r"(a[0]), "r"(a[1]), "r"(a[2]), "r"(a[3]), "r"(b[0]), "r"(b[1]));
}

static __device__ __forceinline__ uint32_t swz(uint32_t off) {
    return off ^ ((off >> 3) & 0x70);
}

static __device__ __forceinline__ uint32_t h2_as_u32(__half2 h) {
    union { __half2 h2; uint32_t u; } c;
    c.h2 = h;
    return c.u;
}

// ---------------------------------------------------------------------------
// conv: adj fp32 -> fp16 (scaled by 2^13, RN). Pure bandwidth.
// ---------------------------------------------------------------------------
__global__ void __launch_bounds__(256) conv_kernel(const float* __restrict__ adj) {
    const size_t n8 = (size_t)NODES * NODES / 8;
    size_t idx = (size_t)blockIdx.x * 256 + threadIdx.x;
    const size_t stride = (size_t)gridDim.x * 256;
    for (size_t i = idx; i < n8; i += stride) {
        const float4* s = (const float4*)(adj + i * 8);
        float4 v0 = s[0];
        float4 v1 = s[1];
        uint4 o;
        o.x = h2_as_u32(__floats2half2_rn(v0.x * ADJ_SCALE, v0.y * ADJ_SCALE));
        o.y = h2_as_u32(__floats2half2_rn(v0.z * ADJ_SCALE, v0.w * ADJ_SCALE));
        o.z = h2_as_u32(__floats2half2_rn(v1.x * ADJ_SCALE, v1.y * ADJ_SCALE));
        o.w = h2_as_u32(__floats2half2_rn(v1.z * ADJ_SCALE, v1.w * ADJ_SCALE));
        *reinterpret_cast<uint4*>(&g_adj_h[i * 8]) = o;
    }
}

// ---------------------------------------------------------------------------
// prep1: Yt_h[b*64+o][j] = fp16( sum_f x[b,j,f] * W2[o,f] )
// W2 computed in-block (no separate prep0 launch).
// block: 256 threads = (o = tid%64, b = tid/64), JT=16 j per block
// ---------------------------------------------------------------------------
__global__ void __launch_bounds__(256) prep1_kernel(const float* __restrict__ x,
                                                    const float* __restrict__ nl_w,
                                                    const float* __restrict__ w_out) {
    __shared__ float xs[BATCH][JT][FEAT];
    __shared__ float w2s[ODIM * (FEAT + 1)];
    const int tid = threadIdx.x;
    const int j0 = blockIdx.x * JT;

    for (int i = tid; i < ODIM * FEAT; i += 256) {
        int o = i >> 6, f = i & 63;
        w2s[o * (FEAT + 1) + f] = INV_SQRT2F * nl_w[f] * w_out[i];
    }

    for (int i4 = tid; i4 < BATCH * JT * (FEAT / 4); i4 += 256) {
        int b = i4 >> 8;
        int r = i4 & 255;
        int j = r >> 4;
        int f4 = r & 15;
        ((float4*)&xs[b][j][0])[f4] =
            ((const float4*)(x + ((size_t)b * NODES + j0 + j) * FEAT))[f4];
    }
    __syncthreads();

    const int o = tid & 63;
    const int b = tid >> 6;

    float w2r[FEAT];
#pragma unroll
    for (int f = 0; f < FEAT; f++) w2r[f] = w2s[o * (FEAT + 1) + f];

    union { __half h[JT]; uint4 u[2]; } ov;
#pragma unroll
    for (int j = 0; j < JT; j++) {
        float acc = 0.f;
#pragma unroll
        for (int f4 = 0; f4 < FEAT / 4; f4++) {
            float4 xv = ((float4*)&xs[b][j][0])[f4];
            acc += xv.x * w2r[f4 * 4 + 0];
            acc += xv.y * w2r[f4 * 4 + 1];
            acc += xv.z * w2r[f4 * 4 + 2];
            acc += xv.w * w2r[f4 * 4 + 3];
        }
        ov.h[j] = __float2half_rn(acc);
    }

    __half* dst = g_Yt_h + (size_t)(b * ODIM + o) * NODES + j0;
    ((uint4*)dst)[0] = ov.u[0];
    ((uint4*)dst)[1] = ov.u[1];
}

// ---------------------------------------------------------------------------
// Main GEMM: out = 2^-13 * (adj_h @ Yt_h^T) + c
// grid 128 = 64 m-tiles x 2 n-tiles, block 256 (8 warps: 2m x 4n, 64x32 each)
// ---------------------------------------------------------------------------
__global__ void __launch_bounds__(256, 1)
gemm_kernel(const float* __restrict__ nl_b, const float* __restrict__ w_out,
            const float* __restrict__ b_out, float* __restrict__ out) {
    extern __shared__ char dynsmem[];
    __shared__ float sc[ODIM];

    const int tid = threadIdx.x;
    const int wid = tid >> 5;
    const int lane = tid & 31;
    const int m0 = (blockIdx.x >> 1) * MT;
    const int n0 = (blockIdx.x & 1) * NT;
    const int wm = wid >> 2;     // 0..1  (m band of 64)
    const int wn = wid & 3;      // 0..3  (n band of 32)

    const uint32_t smem0 = smem_u32(dynsmem);

    // Pre-swizzled per-lane fragment base offsets.
    // A (m16k16 tile mi): x4 mats = rows0-7 k0-7, rows8-15 k0-7,
    //                               rows0-7 k8-15, rows8-15 k8-15  (= a0..a3)
    uint32_t pa[4];
    {
        int r15 = lane & 15;
        int h = lane >> 4;
#pragma unroll
        for (int mi = 0; mi < 4; mi++)
            pa[mi] = swz((uint32_t)((wm * 64 + mi * 16 + r15) * 128 + h * 16));
    }
    // B (two n8 tiles per x4): mats = even k0-7, even k8-15, odd k0-7, odd k8-15
    uint32_t pb[2];
    {
        int tile_sel = lane >> 4;
        int h = (lane >> 3) & 1;
        int rn = lane & 7;
#pragma unroll
        for (int nj = 0; nj < 2; nj++)
            pb[nj] = swz((uint32_t)((wn * 32 + (nj * 2 + tile_sel) * 8 + rn) * 128 + h * 16));
    }

    float acc[4][4][4];
#pragma unroll
    for (int mi = 0; mi < 4; mi++)
#pragma unroll
        for (int ni = 0; ni < 4; ni++)
#pragma unroll
            for (int q = 0; q < 4; q++) acc[mi][ni][q] = 0.f;

    // cooperative chunk load: 2048 x 16B cp.async (8 per thread)
    auto load_chunk = [&](int c) {
        const uint32_t sbase = smem0 + (uint32_t)(c % STAGES) * STAGE_BYTES;
        const int kb = c * KCH;
#pragma unroll
        for (int t = 0; t < 8; t++) {
            int idx = tid + t * 256;            // 0..2047
            int mat = idx >> 10;                // 0=A(adj_h), 1=B(Yt_h)
            int r = (idx >> 3) & 127;           // row
            int seg = idx & 7;                  // 16B segment (8 halfs)
            uint32_t dst = sbase + (uint32_t)mat * A_BYTES +
                           swz((uint32_t)(r * 128 + seg * 16));
            const __half* src = mat
                ? g_Yt_h + (size_t)(n0 + r) * NODES + kb + seg * 8
                : g_adj_h + (size_t)(m0 + r) * NODES + kb + seg * 8;
            cp_async16(dst, src);
        }
    };

    // prologue: 5 chunks in flight
#pragma unroll
    for (int c = 0; c < STAGES - 1; c++) {
        load_chunk(c);
        cp_commit();
    }

    // bias vector (overlaps with prologue loads)
    if (tid < ODIM) {
        float a = b_out[tid];
#pragma unroll 8
        for (int f = 0; f < FEAT; f++) a += nl_b[f] * w_out[tid * FEAT + f];
        sc[tid] = a;
    }

    uint32_t fa[2][4][4];
    uint32_t fb[2][4][2];

    for (int i = 0; i < NCH; i++) {
        const int c = i + STAGES - 1;
        if (c < NCH) load_chunk(c);
        cp_commit();                 // one group per iteration (empty at tail)
        cp_wait<STAGES - 1>();       // chunk i resident
        __syncthreads();

        const uint32_t sbase = smem0 + (uint32_t)(i % STAGES) * STAGE_BYTES;

        auto fetch = [&](int s, int buf) {
            const uint32_t xo = (uint32_t)s << 5;   // k16 step: +32B, XOR-safe
#pragma unroll
            for (int mi = 0; mi < 4; mi++)
                ldsm_x4(fa[buf][mi][0], fa[buf][mi][1],
                        fa[buf][mi][2], fa[buf][mi][3],
                        sbase + (pa[mi] ^ xo));
#pragma unroll
            for (int nj = 0; nj < 2; nj++) {
                uint32_t r0, r1, r2, r3;
                ldsm_x4(r0, r1, r2, r3, sbase + A_BYTES + (pb[nj] ^ xo));
                fb[buf][nj * 2 + 0][0] = r0;
                fb[buf][nj * 2 + 0][1] = r1;
                fb[buf][nj * 2 + 1][0] = r2;
                fb[buf][nj * 2 + 1][1] = r3;
            }
        };

        fetch(0, 0);
#pragma unroll
        for (int s = 0; s < KCH / 16; s++) {        // 4 k16 steps
            if (s < KCH / 16 - 1) fetch(s + 1, (s + 1) & 1);
            const int bf = s & 1;
#pragma unroll
            for (int mi = 0; mi < 4; mi++)
#pragma unroll
                for (int ni = 0; ni < 4; ni++)
                    mma_f16(acc[mi][ni], fa[bf][mi], fb[bf][ni]);
        }
        __syncthreads();
    }

    // epilogue: rescale + bias + scatter to (b, node, o)
    const int qr = lane >> 2;
    const int qc = lane & 3;
#pragma unroll
    for (int mi = 0; mi < 4; mi++) {
        const int row0 = m0 + wm * 64 + mi * 16 + qr;
#pragma unroll
        for (int ni = 0; ni < 4; ni++) {
            const int ng = n0 + wn * 32 + ni * 8 + qc * 2;
            const int b = ng >> 6;
            const int o = ng & 63;
            const float c0 = sc[o];
            const float c1 = sc[o + 1];
            float* d0 = out + ((size_t)b * NODES + row0) * ODIM + o;
            float2 v0 = make_float2(acc[mi][ni][0] * OUT_SCALE + c0,
                                    acc[mi][ni][1] * OUT_SCALE + c1);
            float2 v1 = make_float2(acc[mi][ni][2] * OUT_SCALE + c0,
                                    acc[mi][ni][3] * OUT_SCALE + c1);
            *(float2*)d0 = v0;
            *(float2*)(d0 + 8 * ODIM) = v1;   // row0 + 8
        }
    }
}

// ---------------------------------------------------------------------------
// launch
// ---------------------------------------------------------------------------
extern "C" void kernel_launch(void* const* d_in, const int* in_sizes, int n_in,
                              void* d_out, int out_size) {
    (void)in_sizes; (void)n_in; (void)out_size;
    const float* x     = (const float*)d_in[0];
    const float* adj   = (const float*)d_in[1];
    const float* nl_w  = (const float*)d_in[2];
    const float* nl_b  = (const float*)d_in[3];
    const float* w_out = (const float*)d_in[4];
    const float* b_out = (const float*)d_in[5];
    float* out = (float*)d_out;

    conv_kernel<<<4096, 256>>>(adj);
    prep1_kernel<<<NODES / JT, 256>>>(x, nl_w, w_out);

    cudaFuncSetAttribute(gemm_kernel,
                         cudaFuncAttributeMaxDynamicSharedMemorySize, SMEM_DYN);
    gemm_kernel<<<128, 256, SMEM_DYN>>>(nl_b, w_out, b_out, out);
}